// round 15
// baseline (speedup 1.0000x reference)
#include <cuda_runtime.h>
#include <cuda_fp16.h>
#include <math.h>
#include <stdint.h>

#define N_PTS  32400
#define NBLK   254               // row-blocks of 128 points
#define BLEN   128
#define N_PAD  (NBLK * BLEN)     // 32512
#define C_DIM  512
#define NCLS   19
#define KNN    9
#define NSLOT  127
#define T_SEL  16

#define NCHUNK 8                 // K chunks of 64 halfs (128B rows)
#define NTH    256

// phase-1 smem (byte offsets from 1024-aligned base)
#define ST_BYTES 32768           // stage: A 16K + B 16K
#define SM_DS    65536           // half dd[128][DSH]
#define DSH      138
#define SM_KL    100864
#define SM_SQC   109056
#define SM_SQR   109568
#define SM_MBAR  110080          // full0,full1,empty0,empty1
#define DYNSMEM  (SM_MBAR + 32 + 1536)

#define MERGE_SMEM (3 * 128 * T_SEL * 4)

// ---------------- device globals ----------------
__device__ __align__(128) __half g_swh[(size_t)NBLK * NCHUNK * 8192];
__device__ float    g_feat[(size_t)N_PAD * C_DIM];
__device__ float    g_sq[N_PAD];
__device__ int      g_label[N_PTS];
__device__ uint32_t g_part_k[(size_t)NBLK * NSLOT * T_SEL * BLEN];
__device__ uint32_t g_loc_k[(size_t)NBLK * T_SEL * BLEN];
__device__ int      g_mrg_i[(size_t)N_PAD * T_SEL];

// ---------------- helpers ----------------
__device__ __forceinline__ uint32_t smem_u32(const void* p) {
    uint32_t a;
    asm("{ .reg .u64 t; cvta.to.shared.u64 t, %1; cvt.u32.u64 %0, t; }" : "=r"(a) : "l"(p));
    return a;
}
__device__ __forceinline__ void ldsm_x4(uint32_t* r, uint32_t a) {
    asm volatile("ldmatrix.sync.aligned.m8n8.x4.shared.b16 {%0,%1,%2,%3}, [%4];"
                 : "=r"(r[0]), "=r"(r[1]), "=r"(r[2]), "=r"(r[3]) : "r"(a));
}
__device__ __forceinline__ void mma16816(float* c, const uint32_t* a, const uint32_t* b) {
    asm volatile("mma.sync.aligned.m16n8k16.row.col.f32.f16.f16.f32 "
                 "{%0,%1,%2,%3}, {%4,%5,%6,%7}, {%8,%9}, {%0,%1,%2,%3};"
                 : "+f"(c[0]), "+f"(c[1]), "+f"(c[2]), "+f"(c[3])
                 : "r"(a[0]), "r"(a[1]), "r"(a[2]), "r"(a[3]), "r"(b[0]), "r"(b[1]));
}
__device__ __forceinline__ void bulk_g2s(uint32_t dst, const void* src,
                                         uint32_t bytes, uint32_t mbar) {
    asm volatile("cp.async.bulk.shared::cluster.global.mbarrier::complete_tx::bytes "
                 "[%0], [%1], %2, [%3];"
                 :: "r"(dst), "l"(__cvta_generic_to_global(src)), "r"(bytes), "r"(mbar)
                 : "memory");
}
#define MBAR_INIT(mb, c)  asm volatile("mbarrier.init.shared.b64 [%0], %1;" :: "r"(mb), "r"(c) : "memory")
#define MBAR_ARRIVE(mb)   asm volatile("mbarrier.arrive.shared.b64 _, [%0];" :: "r"(mb) : "memory")
#define MBAR_WAIT(mb, ph) do {                                                   \
    uint32_t _mb = (mb), _ph = (ph), _done;                                      \
    asm volatile("{ .reg .pred p; mbarrier.try_wait.parity.acquire.cta.shared::cta.b64 p, [%1], %2; selp.b32 %0, 1, 0, p; }" \
        : "=r"(_done) : "r"(_mb), "r"(_ph) : "memory");                          \
    if (!_done) {                                                                \
        asm volatile("{ .reg .pred P1; WL_%=: mbarrier.try_wait.parity.acquire.cta.shared::cta.b64 P1, [%0], %1, 0x989680; @P1 bra.uni WD_%=; bra.uni WL_%=; WD_%=: }" \
            :: "r"(_mb), "r"(_ph) : "memory");                                   \
    }                                                                            \
} while (0)

#define INSERT16K(key, kl, kmaxk, kpos)                                          \
    do {                                                                         \
        (kl)[kpos] = (key); kmaxk = (kl)[0]; kpos = 0;                           \
        _Pragma("unroll")                                                        \
        for (int _t = 1; _t < T_SEL; _t++) {                                     \
            uint32_t _v = (kl)[_t];                                              \
            if (_v > kmaxk) { kmaxk = _v; kpos = _t; }                           \
        }                                                                        \
    } while (0)

// ---------------- prep: sq norms + argmax labels ----------------------------
__global__ void prep_kernel(const float* __restrict__ feats,
                            const float* __restrict__ outs) {
    int n = blockIdx.x * blockDim.x + threadIdx.x;
    if (n >= N_PAD) return;
    if (n >= N_PTS) { g_sq[n] = 1e30f; return; }
    float s = 0.f;
#pragma unroll 8
    for (int c = 0; c < C_DIM; c++) {
        float v = feats[(size_t)c * N_PTS + n];
        s = fmaf(v, v, s);
    }
    g_sq[n] = s;
    float best = outs[n];
    int bl = 0;
#pragma unroll
    for (int c = 1; c < NCLS; c++) {
        float v = outs[(size_t)c * N_PTS + n];
        if (v > best) { best = v; bl = c; }
    }
    g_label[n] = bl;
}

// ---------------- tiny pad kernel (positions phase1 as ncu op #5) -----------
__global__ void pad_kernel() {
    int i = threadIdx.x;
    if (N_PTS + i < N_PAD) g_sq[N_PTS + i] = 1e30f;
}

// ---------------- fused split: transpose -> fp16 swizzled + fp32 [n][c] -----
__global__ void split_kernel(const float* __restrict__ feats) {
    __shared__ float t[32][33];
    int n0 = blockIdx.x * 32, c0 = blockIdx.y * 32;
    int n = n0 + threadIdx.x;
    t[threadIdx.y][threadIdx.x] = (n < N_PTS) ? feats[(size_t)(c0 + threadIdx.y) * N_PTS + n] : 0.f;
    __syncthreads();
    int np = n0 + threadIdx.y, cp = c0 + threadIdx.x;
    float x = t[threadIdx.x][threadIdx.y];
    int blk = np >> 7, r = np & 127;
    int kc = cp >> 6, u = (cp >> 3) & 7, b = cp & 7;
    g_swh[((size_t)(blk * NCHUNK + kc)) * 8192 + r * 64 + ((u ^ (r & 7)) << 3) + b]
        = __float2half_rn(x);
    g_feat[(size_t)np * C_DIM + cp] = x;
}

// ---------------- bulk chunk issue (single thread) --------------------------
__device__ __forceinline__ void issue_chunk(uint32_t sb, int stage,
                                            int iblk, int jblk, int kc) {
    uint32_t st = sb + stage * ST_BYTES;
    uint32_t mbar = sb + SM_MBAR + 8 * stage;
    const __half* a = g_swh + ((size_t)(iblk * NCHUNK + kc)) * 8192;
    const __half* b = g_swh + ((size_t)(jblk * NCHUNK + kc)) * 8192;
    asm volatile("fence.proxy.async.shared::cta;" ::: "memory");
    asm volatile("mbarrier.arrive.expect_tx.shared.b64 _, [%0], %1;"
                 :: "r"(mbar), "r"(32768u) : "memory");
    bulk_g2s(st, a, 16384, mbar);
    bulk_g2s(st + 16384, b, 16384, mbar);
}

// ---------------- phase 1: fp16 GEMM + integer-screened top-16 --------------
__global__ __launch_bounds__(NTH, 2)
void phase1_kernel() {
    extern __shared__ char smraw[];
    uint32_t sbr = smem_u32(smraw);
    uint32_t sb = (sbr + 1023u) & ~1023u;
    char* smem = smraw + (sb - sbr);

    const int tid = threadIdx.x;
    const int l = tid & 31, w = tid >> 5;
    const int wm = w >> 2, wn = w & 3;
    const int iblk = blockIdx.x;
    const int q0 = iblk * BLEN;
    const int NU = (iblk < 127) ? 128 : 127;
    const int lrA = l & 15, luA = l >> 4;

    uint32_t* klist = (uint32_t*)(smem + SM_KL);
    float* sqc = (float*)(smem + SM_SQC);
    float* sqr = (float*)(smem + SM_SQR);
    __half* dsh = (__half*)(smem + SM_DS);
    const unsigned short* dsu = (const unsigned short*)dsh;

    uint32_t* kl = klist + tid * T_SEL;
    uint32_t kmaxk = 0xFFFFFFFFu, kmax16 = 0xFFFFu;
    int kpos = 0;
    if (tid < BLEN) {
        sqr[tid] = g_sq[q0 + tid];
#pragma unroll
        for (int t = 0; t < T_SEL; t++) kl[t] = 0xFFFFFFFFu;
    }
    if (tid == 0) {
        MBAR_INIT(sb + SM_MBAR, 1);        // full0
        MBAR_INIT(sb + SM_MBAR + 8, 1);    // full1
        MBAR_INIT(sb + SM_MBAR + 16, 8);   // empty0
        MBAR_INIT(sb + SM_MBAR + 24, 8);   // empty1
    }
    __syncthreads();
    int ph0 = 0, ph1 = 0;
    int pe0 = 0, pe1 = 1;

    if (tid == 0) issue_chunk(sb, 0, iblk, iblk, 0);

    for (int d = 0; d < NU; d++) {
        const int jblk = (iblk + d) % NBLK;
        const int j0 = jblk * BLEN;
        if (tid < BLEN) sqc[tid] = g_sq[j0 + tid];
        __syncthreads();   // sqc visible to all (dump reads it)

        float acc[4][4][4];
#pragma unroll
        for (int mb = 0; mb < 4; mb++)
#pragma unroll
            for (int nb = 0; nb < 4; nb++)
#pragma unroll
                for (int r = 0; r < 4; r++) acc[mb][nb][r] = 0.f;

        for (int kc = 0; kc < NCHUNK; kc++) {
            const int stage = kc & 1;
            if (tid == 0) {
                if (kc + 1 < NCHUNK) {
                    int ns = (kc + 1) & 1;
                    if (ns == 0) { MBAR_WAIT(sb + SM_MBAR + 16, pe0); pe0 ^= 1; }
                    else         { MBAR_WAIT(sb + SM_MBAR + 24, pe1); pe1 ^= 1; }
                    issue_chunk(sb, ns, iblk, jblk, kc + 1);
                } else if (d + 1 < NU) {
                    MBAR_WAIT(sb + SM_MBAR + 16, pe0); pe0 ^= 1;
                    issue_chunk(sb, 0, iblk, (iblk + d + 1) % NBLK, 0);
                }
            }
            if (stage == 0) { MBAR_WAIT(sb + SM_MBAR, ph0); ph0 ^= 1; }
            else           { MBAR_WAIT(sb + SM_MBAR + 8, ph1); ph1 ^= 1; }

            uint32_t stg = sb + stage * ST_BYTES;
            uint32_t ab = stg, bb = stg + 16384;
#pragma unroll
            for (int k16 = 0; k16 < 4; k16++) {
                int u = k16 * 2;
                uint32_t a[4][4], b[4][2];
#pragma unroll
                for (int mb = 0; mb < 4; mb++) {
                    int row = wm * 64 + mb * 16 + lrA;
                    ldsm_x4(a[mb], ab + row * 128 + (((u + luA) ^ (row & 7)) << 4));
                }
#pragma unroll
                for (int nbp = 0; nbp < 2; nbp++) {
                    int rowb = wn * 32 + (nbp * 2 + (l >> 4)) * 8 + (l & 7);
                    int ku = u + ((l >> 3) & 1);
                    uint32_t tmp[4];
                    ldsm_x4(tmp, bb + rowb * 128 + ((ku ^ (rowb & 7)) << 4));
                    b[nbp * 2][0] = tmp[0]; b[nbp * 2][1] = tmp[1];
                    b[nbp * 2 + 1][0] = tmp[2]; b[nbp * 2 + 1][1] = tmp[3];
                }
#pragma unroll
                for (int mb = 0; mb < 4; mb++)
#pragma unroll
                    for (int nb = 0; nb < 4; nb++)
                        mma16816(acc[mb][nb], a[mb], b[nb]);
            }
            if (l == 0) MBAR_ARRIVE(sb + SM_MBAR + 16 + 8 * stage);
        }

        // ---- dump CLAMPED HALF DISTANCES transposed: dsh[n][q] -------------
#pragma unroll
        for (int mb = 0; mb < 4; mb++) {
            int q = wm * 64 + mb * 16 + (l >> 2);
            float s0 = sqr[q], s1 = sqr[q + 8];
#pragma unroll
            for (int nb = 0; nb < 4; nb++) {
                int n = wn * 32 + nb * 8 + (l & 3) * 2;
                float cn0 = sqc[n], cn1 = sqc[n + 1];
                dsh[(size_t)n * DSH + q] =
                    __float2half_rn(fmaxf(s0 + cn0 - 2.f * acc[mb][nb][0], 0.f));
                dsh[(size_t)(n + 1) * DSH + q] =
                    __float2half_rn(fmaxf(s0 + cn1 - 2.f * acc[mb][nb][1], 0.f));
                dsh[(size_t)n * DSH + q + 8] =
                    __float2half_rn(fmaxf(s1 + cn0 - 2.f * acc[mb][nb][2], 0.f));
                dsh[(size_t)(n + 1) * DSH + q + 8] =
                    __float2half_rn(fmaxf(s1 + cn1 - 2.f * acc[mb][nb][3], 0.f));
            }
        }
        __syncthreads();

        if (tid < BLEN) {
            // ---- row scan: pure integer screening on stored half bits ------
            for (int n0 = 0; n0 < BLEN; n0 += 8) {
                uint32_t v[8];
                bool any = false;
#pragma unroll
                for (int i = 0; i < 8; i++) {
                    v[i] = dsu[(size_t)(n0 + i) * DSH + tid];
                    any |= (v[i] <= kmax16);
                }
                if (any) {
#pragma unroll
                    for (int i = 0; i < 8; i++)
                        if (v[i] <= kmax16) {
                            uint32_t key = (v[i] << 16) | (uint32_t)(j0 + n0 + i);
                            if (key < kmaxk) {
                                INSERT16K(key, kl, kmaxk, kpos);
                                kmax16 = kmaxk >> 16;
                            }
                        }
                }
            }
        } else if (d > 0) {
            // ---- col scan: contiguous words, integer screening -------------
            int c = tid - BLEN;
            uint32_t cl[T_SEL];
#pragma unroll
            for (int t = 0; t < T_SEL; t++) cl[t] = 0xFFFFFFFFu;
            uint32_t cmaxk = 0xFFFFFFFFu, cmax16 = 0xFFFFu;
            int cpos = 0;
            const uint32_t* drow = (const uint32_t*)(dsh + (size_t)c * DSH);
            for (int q2 = 0; q2 < BLEN; q2 += 8) {
                uint32_t wv[4];
                bool any = false;
#pragma unroll
                for (int j = 0; j < 4; j++) {
                    wv[j] = drow[(q2 >> 1) + j];
                    any |= ((wv[j] & 0xFFFFu) <= cmax16) | ((wv[j] >> 16) <= cmax16);
                }
                if (any) {
#pragma unroll
                    for (int j = 0; j < 4; j++) {
                        uint32_t lo = wv[j] & 0xFFFFu, hi = wv[j] >> 16;
                        if (lo <= cmax16) {
                            uint32_t key = (lo << 16) | (uint32_t)(q0 + q2 + 2 * j);
                            if (key < cmaxk) {
                                INSERT16K(key, cl, cmaxk, cpos);
                                cmax16 = cmaxk >> 16;
                            }
                        }
                        if (hi <= cmax16) {
                            uint32_t key = (hi << 16) | (uint32_t)(q0 + q2 + 2 * j + 1);
                            if (key < cmaxk) {
                                INSERT16K(key, cl, cmaxk, cpos);
                                cmax16 = cmaxk >> 16;
                            }
                        }
                    }
                }
            }
            size_t base = (((size_t)jblk * NSLOT + (d - 1)) * T_SEL) * BLEN + c;
#pragma unroll
            for (int t = 0; t < T_SEL; t++)
                g_part_k[base + (size_t)t * BLEN] = cl[t];
        }
        __syncthreads();
    }

    if (tid < BLEN) {
        size_t base = (size_t)iblk * T_SEL * BLEN + tid;
#pragma unroll
        for (int t = 0; t < T_SEL; t++)
            g_loc_k[base + (size_t)t * BLEN] = kl[t];
    }
}

// ---------------- merge: 4 subs per query, packed keys ----------------------
__global__ __launch_bounds__(512)
void merge_kernel() {
    extern __shared__ uint32_t msub[];

    const int blk = blockIdx.x;
    const int tid = threadIdx.x;
    const int sub = tid >> 7, q = tid & 127;
    const int smax = 126 + (blk >= 127 ? 1 : 0);

    uint32_t kl[T_SEL];
    if (sub == 0) {
        size_t lb = (size_t)blk * T_SEL * BLEN + q;
#pragma unroll
        for (int t = 0; t < T_SEL; t++) kl[t] = g_loc_k[lb + (size_t)t * BLEN];
    } else {
#pragma unroll
        for (int t = 0; t < T_SEL; t++) kl[t] = 0xFFFFFFFFu;
    }
    uint32_t kmaxk = kl[0];
    int kpos = 0;
#pragma unroll
    for (int t = 1; t < T_SEL; t++)
        if (kl[t] > kmaxk) { kmaxk = kl[t]; kpos = t; }

    const int s0 = (sub == 0) ? 0 : 31 + (sub - 1) * 32;
    const int s1 = (sub == 0) ? 31 : s0 + 32;
    for (int s = s0; s < s1 && s < smax; s++) {
        size_t base = (((size_t)blk * NSLOT + s) * T_SEL) * BLEN + q;
#pragma unroll
        for (int t0 = 0; t0 < T_SEL; t0 += 8) {
            uint32_t v[8];
            bool any = false;
#pragma unroll
            for (int i = 0; i < 8; i++) {
                v[i] = g_part_k[base + (size_t)(t0 + i) * BLEN];
                any |= (v[i] < kmaxk);
            }
            if (any) {
#pragma unroll
                for (int i = 0; i < 8; i++)
                    if (v[i] < kmaxk) INSERT16K(v[i], kl, kmaxk, kpos);
            }
        }
    }

    if (sub > 0) {
        uint32_t* dst = msub + (size_t)((sub - 1) * 128 + q) * T_SEL;
#pragma unroll
        for (int t = 0; t < T_SEL; t++) dst[t] = kl[t];
    }
    __syncthreads();

    if (sub == 0) {
#pragma unroll
        for (int s = 0; s < 3; s++) {
            const uint32_t* ol = msub + (size_t)(s * 128 + q) * T_SEL;
#pragma unroll
            for (int t = 0; t < T_SEL; t++) {
                uint32_t v = ol[t];
                if (v < kmaxk) INSERT16K(v, kl, kmaxk, kpos);
            }
        }
        size_t ob = (size_t)(blk * BLEN + q) * T_SEL;
#pragma unroll
        for (int t = 0; t < T_SEL; t++)
            g_mrg_i[ob + t] = (int)(kl[t] & 0xFFFFu);
    }
}

// ---------------- refine: exact fp32 on 16 candidates, 2-way ILP ------------
__global__ __launch_bounds__(256)
void refine_kernel(float* __restrict__ out) {
    const int warp = threadIdx.x >> 5, l = threadIdx.x & 31;
    const int q = blockIdx.x * 8 + warp;
    __shared__ float sd[8][T_SEL];
    __shared__ int   si[8][T_SEL];
    if (q >= N_PTS) return;

    const float4* fb = (const float4*)g_feat;
    float4 qv[4];
#pragma unroll
    for (int j = 0; j < 4; j++) qv[j] = fb[(size_t)q * 128 + l + 32 * j];
    float sqq = g_sq[q];

    for (int c = 0; c < T_SEL; c += 2) {
        int i0 = g_mrg_i[(size_t)q * T_SEL + c];
        int i1 = g_mrg_i[(size_t)q * T_SEL + c + 1];
        float a0 = 0.f, a1 = 0.f;
#pragma unroll
        for (int j = 0; j < 4; j++) {
            float4 v0 = fb[(size_t)i0 * 128 + l + 32 * j];
            float4 v1 = fb[(size_t)i1 * 128 + l + 32 * j];
            a0 = fmaf(qv[j].x, v0.x, a0); a0 = fmaf(qv[j].y, v0.y, a0);
            a0 = fmaf(qv[j].z, v0.z, a0); a0 = fmaf(qv[j].w, v0.w, a0);
            a1 = fmaf(qv[j].x, v1.x, a1); a1 = fmaf(qv[j].y, v1.y, a1);
            a1 = fmaf(qv[j].z, v1.z, a1); a1 = fmaf(qv[j].w, v1.w, a1);
        }
#pragma unroll
        for (int o = 16; o > 0; o >>= 1) {
            a0 += __shfl_xor_sync(0xFFFFFFFF, a0, o);
            a1 += __shfl_xor_sync(0xFFFFFFFF, a1, o);
        }
        if (l == 0) {
            sd[warp][c]     = sqq + g_sq[i0] - 2.f * a0;
            si[warp][c]     = i0;
            sd[warp][c + 1] = sqq + g_sq[i1] - 2.f * a1;
            si[warp][c + 1] = i1;
        }
    }
    __syncwarp();

    if (l == 0) {
        float kd[KNN]; int ki[KNN];
#pragma unroll
        for (int t = 0; t < KNN; t++) { kd[t] = INFINITY; ki[t] = 0; }
        float kmax = INFINITY; int kpos = 0;
#pragma unroll
        for (int c = 0; c < T_SEL; c++) {
            float dd = sd[warp][c];
            if (dd < kmax) {
                kd[kpos] = dd; ki[kpos] = si[warp][c];
                kmax = kd[0]; kpos = 0;
#pragma unroll
                for (int t = 1; t < KNN; t++)
                    if (kd[t] > kmax) { kmax = kd[t]; kpos = t; }
            }
        }
        int cnt[NCLS];
#pragma unroll
        for (int c = 0; c < NCLS; c++) cnt[c] = 0;
#pragma unroll
        for (int t = 0; t < KNN; t++) cnt[g_label[ki[t]]]++;
        float s = 0.f;
#pragma unroll
        for (int c = 0; c < NCLS; c++) {
            if (cnt[c] > 0) {
                float p = (float)cnt[c] * (1.f / 9.f);
                s -= p * logf(p + 1e-6f);
            }
        }
        out[q] = s * (1.f / logf(19.f));
    }
}

// ---------------- launch ----------------------------------------------------
extern "C" void kernel_launch(void* const* d_in, const int* in_sizes, int n_in,
                              void* d_out, int out_size) {
    const float* feats = (const float*)d_in[0];
    const float* outs  = (const float*)d_in[1];
    float* out = (float*)d_out;

    cudaFuncSetAttribute(phase1_kernel,
                         cudaFuncAttributeMaxDynamicSharedMemorySize, DYNSMEM);
    cudaFuncSetAttribute(merge_kernel,
                         cudaFuncAttributeMaxDynamicSharedMemorySize, MERGE_SMEM);

    cudaMemsetAsync(out, 0, (size_t)out_size * sizeof(float), 0);
    prep_kernel<<<(N_PAD + 255) / 256, 256>>>(feats, outs);
    {
        dim3 g(N_PAD / 32, C_DIM / 32), b(32, 32);
        split_kernel<<<g, b>>>(feats);
    }
    pad_kernel<<<1, 128>>>();                      // op #4 -> phase1 is op #5
    phase1_kernel<<<NBLK, NTH, DYNSMEM>>>();       // ncu target
    merge_kernel<<<NBLK, 512, MERGE_SMEM>>>();
    refine_kernel<<<(N_PTS + 7) / 8, 256>>>(out);
}

// round 16
// speedup vs baseline: 1.7454x; 1.7454x over previous
#include <cuda_runtime.h>
#include <cuda_fp16.h>
#include <math.h>
#include <stdint.h>

#define N_PTS  32400
#define NBLK   254               // row-blocks of 128 points
#define BLEN   128
#define N_PAD  (NBLK * BLEN)     // 32512
#define C_DIM  512
#define NCLS   19
#define KNN    9
#define NSLOT  127
#define T_SEL  16

#define NCHUNK 8                 // K chunks of 64 halfs (128B rows)
#define NTH    256

// phase-1 smem (byte offsets from 1024-aligned base)
#define ST_BYTES 32768           // stage: A 16K + B 16K
#define SM_DS    65536           // half dd[128][DSH]
#define DSH      138
#define SM_KL    100864
#define SM_SQC   109056
#define SM_SQR   109568
#define SM_MBAR  110080          // full0,full1,empty0,empty1
#define DYNSMEM  (SM_MBAR + 32 + 1536)

#define MERGE_SMEM (3 * 128 * T_SEL * 4)

// ---------------- device globals ----------------
__device__ __align__(128) __half g_swh[(size_t)NBLK * NCHUNK * 8192];
__device__ float    g_feat[(size_t)N_PAD * C_DIM];
__device__ float    g_sq[N_PAD];
__device__ int      g_label[N_PTS];
__device__ uint32_t g_kth[N_PAD];        // stale per-query 16th-best key
__device__ uint32_t g_part_k[(size_t)NBLK * NSLOT * T_SEL * BLEN];
__device__ uint32_t g_loc_k[(size_t)NBLK * T_SEL * BLEN];
__device__ int      g_mrg_i[(size_t)N_PAD * T_SEL];

// ---------------- helpers ----------------
__device__ __forceinline__ uint32_t smem_u32(const void* p) {
    uint32_t a;
    asm("{ .reg .u64 t; cvta.to.shared.u64 t, %1; cvt.u32.u64 %0, t; }" : "=r"(a) : "l"(p));
    return a;
}
__device__ __forceinline__ void ldsm_x4(uint32_t* r, uint32_t a) {
    asm volatile("ldmatrix.sync.aligned.m8n8.x4.shared.b16 {%0,%1,%2,%3}, [%4];"
                 : "=r"(r[0]), "=r"(r[1]), "=r"(r[2]), "=r"(r[3]) : "r"(a));
}
__device__ __forceinline__ void mma16816(float* c, const uint32_t* a, const uint32_t* b) {
    asm volatile("mma.sync.aligned.m16n8k16.row.col.f32.f16.f16.f32 "
                 "{%0,%1,%2,%3}, {%4,%5,%6,%7}, {%8,%9}, {%0,%1,%2,%3};"
                 : "+f"(c[0]), "+f"(c[1]), "+f"(c[2]), "+f"(c[3])
                 : "r"(a[0]), "r"(a[1]), "r"(a[2]), "r"(a[3]), "r"(b[0]), "r"(b[1]));
}
__device__ __forceinline__ void bulk_g2s(uint32_t dst, const void* src,
                                         uint32_t bytes, uint32_t mbar) {
    asm volatile("cp.async.bulk.shared::cluster.global.mbarrier::complete_tx::bytes "
                 "[%0], [%1], %2, [%3];"
                 :: "r"(dst), "l"(__cvta_generic_to_global(src)), "r"(bytes), "r"(mbar)
                 : "memory");
}
#define MBAR_INIT(mb, c)  asm volatile("mbarrier.init.shared.b64 [%0], %1;" :: "r"(mb), "r"(c) : "memory")
#define MBAR_ARRIVE(mb)   asm volatile("mbarrier.arrive.shared.b64 _, [%0];" :: "r"(mb) : "memory")
#define MBAR_WAIT(mb, ph) do {                                                   \
    uint32_t _mb = (mb), _ph = (ph), _done;                                      \
    asm volatile("{ .reg .pred p; mbarrier.try_wait.parity.acquire.cta.shared::cta.b64 p, [%1], %2; selp.b32 %0, 1, 0, p; }" \
        : "=r"(_done) : "r"(_mb), "r"(_ph) : "memory");                          \
    if (!_done) {                                                                \
        asm volatile("{ .reg .pred P1; WL_%=: mbarrier.try_wait.parity.acquire.cta.shared::cta.b64 P1, [%0], %1, 0x989680; @P1 bra.uni WD_%=; bra.uni WL_%=; WD_%=: }" \
            :: "r"(_mb), "r"(_ph) : "memory");                                   \
    }                                                                            \
} while (0)

#define INSERT16K(key, kl, kmaxk, kpos)                                          \
    do {                                                                         \
        (kl)[kpos] = (key); kmaxk = (kl)[0]; kpos = 0;                           \
        _Pragma("unroll")                                                        \
        for (int _t = 1; _t < T_SEL; _t++) {                                     \
            uint32_t _v = (kl)[_t];                                              \
            if (_v > kmaxk) { kmaxk = _v; kpos = _t; }                           \
        }                                                                        \
    } while (0)

// ---------------- prep: sq norms + labels + threshold init ------------------
__global__ void prep_kernel(const float* __restrict__ feats,
                            const float* __restrict__ outs) {
    int n = blockIdx.x * blockDim.x + threadIdx.x;
    if (n >= N_PAD) return;
    g_kth[n] = 0xFFFFFFFFu;
    if (n >= N_PTS) { g_sq[n] = 1e30f; return; }
    float s = 0.f;
#pragma unroll 8
    for (int c = 0; c < C_DIM; c++) {
        float v = feats[(size_t)c * N_PTS + n];
        s = fmaf(v, v, s);
    }
    g_sq[n] = s;
    float best = outs[n];
    int bl = 0;
#pragma unroll
    for (int c = 1; c < NCLS; c++) {
        float v = outs[(size_t)c * N_PTS + n];
        if (v > best) { best = v; bl = c; }
    }
    g_label[n] = bl;
}

// ---------------- tiny pad kernel (positions phase1 as ncu op #5) -----------
__global__ void pad_kernel() {
    int i = threadIdx.x;
    if (N_PTS + i < N_PAD) g_sq[N_PTS + i] = 1e30f;
}

// ---------------- fused split: transpose -> fp16 swizzled + fp32 [n][c] -----
__global__ void split_kernel(const float* __restrict__ feats) {
    __shared__ float t[32][33];
    int n0 = blockIdx.x * 32, c0 = blockIdx.y * 32;
    int n = n0 + threadIdx.x;
    t[threadIdx.y][threadIdx.x] = (n < N_PTS) ? feats[(size_t)(c0 + threadIdx.y) * N_PTS + n] : 0.f;
    __syncthreads();
    int np = n0 + threadIdx.y, cp = c0 + threadIdx.x;
    float x = t[threadIdx.x][threadIdx.y];
    int blk = np >> 7, r = np & 127;
    int kc = cp >> 6, u = (cp >> 3) & 7, b = cp & 7;
    g_swh[((size_t)(blk * NCHUNK + kc)) * 8192 + r * 64 + ((u ^ (r & 7)) << 3) + b]
        = __float2half_rn(x);
    g_feat[(size_t)np * C_DIM + cp] = x;
}

// ---------------- bulk chunk issue (single thread) --------------------------
__device__ __forceinline__ void issue_chunk(uint32_t sb, int stage,
                                            int iblk, int jblk, int kc) {
    uint32_t st = sb + stage * ST_BYTES;
    uint32_t mbar = sb + SM_MBAR + 8 * stage;
    const __half* a = g_swh + ((size_t)(iblk * NCHUNK + kc)) * 8192;
    const __half* b = g_swh + ((size_t)(jblk * NCHUNK + kc)) * 8192;
    asm volatile("fence.proxy.async.shared::cta;" ::: "memory");
    asm volatile("mbarrier.arrive.expect_tx.shared.b64 _, [%0], %1;"
                 :: "r"(mbar), "r"(32768u) : "memory");
    bulk_g2s(st, a, 16384, mbar);
    bulk_g2s(st + 16384, b, 16384, mbar);
}

// ---------------- phase 1: fp16 GEMM + integer-screened top-16 --------------
__global__ __launch_bounds__(NTH, 2)
void phase1_kernel() {
    extern __shared__ char smraw[];
    uint32_t sbr = smem_u32(smraw);
    uint32_t sb = (sbr + 1023u) & ~1023u;
    char* smem = smraw + (sb - sbr);

    const int tid = threadIdx.x;
    const int l = tid & 31, w = tid >> 5;
    const int wm = w >> 2, wn = w & 3;
    const int iblk = blockIdx.x;
    const int q0 = iblk * BLEN;
    const int NU = (iblk < 127) ? 128 : 127;
    const int lrA = l & 15, luA = l >> 4;

    uint32_t* klist = (uint32_t*)(smem + SM_KL);
    float* sqc = (float*)(smem + SM_SQC);
    float* sqr = (float*)(smem + SM_SQR);
    __half* dsh = (__half*)(smem + SM_DS);
    const unsigned short* dsu = (const unsigned short*)dsh;

    uint32_t* kl = klist + tid * T_SEL;
    uint32_t kmaxk = 0xFFFFFFFFu, kmax16 = 0xFFFFu;
    int kpos = 0;
    if (tid < BLEN) {
        sqr[tid] = g_sq[q0 + tid];
#pragma unroll
        for (int t = 0; t < T_SEL; t++) kl[t] = 0xFFFFFFFFu;
    }
    if (tid == 0) {
        MBAR_INIT(sb + SM_MBAR, 1);        // full0
        MBAR_INIT(sb + SM_MBAR + 8, 1);    // full1
        MBAR_INIT(sb + SM_MBAR + 16, 8);   // empty0
        MBAR_INIT(sb + SM_MBAR + 24, 8);   // empty1
    }
    __syncthreads();
    int ph0 = 0, ph1 = 0;
    int pe0 = 0, pe1 = 1;

    if (tid == 0) issue_chunk(sb, 0, iblk, iblk, 0);

    for (int d = 0; d < NU; d++) {
        const int jblk = (iblk + d) % NBLK;
        const int j0 = jblk * BLEN;
        // sqc write is ordered before the dump's reads by the empty-mbarrier
        // chain (producer can't issue chunk k>=2 until all warps arrived
        // empty(k-2), which is after their sqc store) -> no barrier needed.
        if (tid < BLEN) sqc[tid] = g_sq[j0 + tid];
        // col screen: stale owner threshold for this unit's col-queries
        uint32_t kth16 = 0xFFFFu;
        if (tid >= BLEN && d > 0)
            kth16 = (*(volatile uint32_t*)&g_kth[j0 + (tid - BLEN)]) >> 16;

        float acc[4][4][4];
#pragma unroll
        for (int mb = 0; mb < 4; mb++)
#pragma unroll
            for (int nb = 0; nb < 4; nb++)
#pragma unroll
                for (int r = 0; r < 4; r++) acc[mb][nb][r] = 0.f;

        for (int kc = 0; kc < NCHUNK; kc++) {
            const int stage = kc & 1;
            if (tid == 0) {
                if (kc + 1 < NCHUNK) {
                    int ns = (kc + 1) & 1;
                    if (ns == 0) { MBAR_WAIT(sb + SM_MBAR + 16, pe0); pe0 ^= 1; }
                    else         { MBAR_WAIT(sb + SM_MBAR + 24, pe1); pe1 ^= 1; }
                    issue_chunk(sb, ns, iblk, jblk, kc + 1);
                } else if (d + 1 < NU) {
                    MBAR_WAIT(sb + SM_MBAR + 16, pe0); pe0 ^= 1;
                    issue_chunk(sb, 0, iblk, (iblk + d + 1) % NBLK, 0);
                }
            }
            if (stage == 0) { MBAR_WAIT(sb + SM_MBAR, ph0); ph0 ^= 1; }
            else           { MBAR_WAIT(sb + SM_MBAR + 8, ph1); ph1 ^= 1; }

            uint32_t stg = sb + stage * ST_BYTES;
            uint32_t ab = stg, bb = stg + 16384;
#pragma unroll
            for (int k16 = 0; k16 < 4; k16++) {
                int u = k16 * 2;
                uint32_t a[4][4], b[4][2];
#pragma unroll
                for (int mb = 0; mb < 4; mb++) {
                    int row = wm * 64 + mb * 16 + lrA;
                    ldsm_x4(a[mb], ab + row * 128 + (((u + luA) ^ (row & 7)) << 4));
                }
#pragma unroll
                for (int nbp = 0; nbp < 2; nbp++) {
                    int rowb = wn * 32 + (nbp * 2 + (l >> 4)) * 8 + (l & 7);
                    int ku = u + ((l >> 3) & 1);
                    uint32_t tmp[4];
                    ldsm_x4(tmp, bb + rowb * 128 + ((ku ^ (rowb & 7)) << 4));
                    b[nbp * 2][0] = tmp[0]; b[nbp * 2][1] = tmp[1];
                    b[nbp * 2 + 1][0] = tmp[2]; b[nbp * 2 + 1][1] = tmp[3];
                }
#pragma unroll
                for (int mb = 0; mb < 4; mb++)
#pragma unroll
                    for (int nb = 0; nb < 4; nb++)
                        mma16816(acc[mb][nb], a[mb], b[nb]);
            }
            if (l == 0) MBAR_ARRIVE(sb + SM_MBAR + 16 + 8 * stage);
        }

        // ---- dump CLAMPED HALF DISTANCES transposed: dsh[n][q] -------------
#pragma unroll
        for (int mb = 0; mb < 4; mb++) {
            int q = wm * 64 + mb * 16 + (l >> 2);
            float s0 = sqr[q], s1 = sqr[q + 8];
#pragma unroll
            for (int nb = 0; nb < 4; nb++) {
                int n = wn * 32 + nb * 8 + (l & 3) * 2;
                float cn0 = sqc[n], cn1 = sqc[n + 1];
                dsh[(size_t)n * DSH + q] =
                    __float2half_rn(fmaxf(s0 + cn0 - 2.f * acc[mb][nb][0], 0.f));
                dsh[(size_t)(n + 1) * DSH + q] =
                    __float2half_rn(fmaxf(s0 + cn1 - 2.f * acc[mb][nb][1], 0.f));
                dsh[(size_t)n * DSH + q + 8] =
                    __float2half_rn(fmaxf(s1 + cn0 - 2.f * acc[mb][nb][2], 0.f));
                dsh[(size_t)(n + 1) * DSH + q + 8] =
                    __float2half_rn(fmaxf(s1 + cn1 - 2.f * acc[mb][nb][3], 0.f));
            }
        }
        __syncthreads();

        if (tid < BLEN) {
            // ---- row scan: integer screening on stored half bits -----------
            for (int n0 = 0; n0 < BLEN; n0 += 8) {
                uint32_t v[8];
                bool any = false;
#pragma unroll
                for (int i = 0; i < 8; i++) {
                    v[i] = dsu[(size_t)(n0 + i) * DSH + tid];
                    any |= (v[i] <= kmax16);
                }
                if (any) {
#pragma unroll
                    for (int i = 0; i < 8; i++)
                        if (v[i] <= kmax16) {
                            uint32_t key = (v[i] << 16) | (uint32_t)(j0 + n0 + i);
                            if (key < kmaxk) {
                                INSERT16K(key, kl, kmaxk, kpos);
                                kmax16 = kmaxk >> 16;
                            }
                        }
                }
            }
            // publish running 16th-best for stale col screening elsewhere
            g_kth[q0 + tid] = kmaxk;
        } else if (d > 0) {
            // ---- col scan: integer screen vs min(local, stale owner) -------
            int c = tid - BLEN;
            uint32_t cl[T_SEL];
#pragma unroll
            for (int t = 0; t < T_SEL; t++) cl[t] = 0xFFFFFFFFu;
            uint32_t cmaxk = 0xFFFFFFFFu, cmax16 = 0xFFFFu;
            uint32_t scr = (kth16 < cmax16) ? kth16 : cmax16;
            int cpos = 0;
            const uint32_t* drow = (const uint32_t*)(dsh + (size_t)c * DSH);
            for (int q2 = 0; q2 < BLEN; q2 += 8) {
                uint32_t wv[4];
                bool any = false;
#pragma unroll
                for (int j = 0; j < 4; j++) {
                    wv[j] = drow[(q2 >> 1) + j];
                    any |= ((wv[j] & 0xFFFFu) <= scr) | ((wv[j] >> 16) <= scr);
                }
                if (any) {
#pragma unroll
                    for (int j = 0; j < 4; j++) {
                        uint32_t lo = wv[j] & 0xFFFFu, hi = wv[j] >> 16;
                        if (lo <= scr) {
                            uint32_t key = (lo << 16) | (uint32_t)(q0 + q2 + 2 * j);
                            if (key < cmaxk) {
                                INSERT16K(key, cl, cmaxk, cpos);
                                cmax16 = cmaxk >> 16;
                                scr = (kth16 < cmax16) ? kth16 : cmax16;
                            }
                        }
                        if (hi <= scr) {
                            uint32_t key = (hi << 16) | (uint32_t)(q0 + q2 + 2 * j + 1);
                            if (key < cmaxk) {
                                INSERT16K(key, cl, cmaxk, cpos);
                                cmax16 = cmaxk >> 16;
                                scr = (kth16 < cmax16) ? kth16 : cmax16;
                            }
                        }
                    }
                }
            }
            size_t base = (((size_t)jblk * NSLOT + (d - 1)) * T_SEL) * BLEN + c;
#pragma unroll
            for (int t = 0; t < T_SEL; t++)
                g_part_k[base + (size_t)t * BLEN] = cl[t];
        }
        __syncthreads();
    }

    if (tid < BLEN) {
        size_t base = (size_t)iblk * T_SEL * BLEN + tid;
#pragma unroll
        for (int t = 0; t < T_SEL; t++)
            g_loc_k[base + (size_t)t * BLEN] = kl[t];
    }
}

// ---------------- merge: 4 subs per query, packed keys ----------------------
__global__ __launch_bounds__(512)
void merge_kernel() {
    extern __shared__ uint32_t msub[];

    const int blk = blockIdx.x;
    const int tid = threadIdx.x;
    const int sub = tid >> 7, q = tid & 127;
    const int smax = 126 + (blk >= 127 ? 1 : 0);

    uint32_t kl[T_SEL];
    if (sub == 0) {
        size_t lb = (size_t)blk * T_SEL * BLEN + q;
#pragma unroll
        for (int t = 0; t < T_SEL; t++) kl[t] = g_loc_k[lb + (size_t)t * BLEN];
    } else {
#pragma unroll
        for (int t = 0; t < T_SEL; t++) kl[t] = 0xFFFFFFFFu;
    }
    uint32_t kmaxk = kl[0];
    int kpos = 0;
#pragma unroll
    for (int t = 1; t < T_SEL; t++)
        if (kl[t] > kmaxk) { kmaxk = kl[t]; kpos = t; }

    const int s0 = (sub == 0) ? 0 : 31 + (sub - 1) * 32;
    const int s1 = (sub == 0) ? 31 : s0 + 32;
    for (int s = s0; s < s1 && s < smax; s++) {
        size_t base = (((size_t)blk * NSLOT + s) * T_SEL) * BLEN + q;
#pragma unroll
        for (int t0 = 0; t0 < T_SEL; t0 += 8) {
            uint32_t v[8];
            bool any = false;
#pragma unroll
            for (int i = 0; i < 8; i++) {
                v[i] = g_part_k[base + (size_t)(t0 + i) * BLEN];
                any |= (v[i] < kmaxk);
            }
            if (any) {
#pragma unroll
                for (int i = 0; i < 8; i++)
                    if (v[i] < kmaxk) INSERT16K(v[i], kl, kmaxk, kpos);
            }
        }
    }

    if (sub > 0) {
        uint32_t* dst = msub + (size_t)((sub - 1) * 128 + q) * T_SEL;
#pragma unroll
        for (int t = 0; t < T_SEL; t++) dst[t] = kl[t];
    }
    __syncthreads();

    if (sub == 0) {
#pragma unroll
        for (int s = 0; s < 3; s++) {
            const uint32_t* ol = msub + (size_t)(s * 128 + q) * T_SEL;
#pragma unroll
            for (int t = 0; t < T_SEL; t++) {
                uint32_t v = ol[t];
                if (v < kmaxk) INSERT16K(v, kl, kmaxk, kpos);
            }
        }
        size_t ob = (size_t)(blk * BLEN + q) * T_SEL;
#pragma unroll
        for (int t = 0; t < T_SEL; t++)
            g_mrg_i[ob + t] = (int)(kl[t] & 0xFFFFu);
    }
}

// ---------------- refine: exact fp32 on 16 candidates, 2-way ILP ------------
__global__ __launch_bounds__(256)
void refine_kernel(float* __restrict__ out) {
    const int warp = threadIdx.x >> 5, l = threadIdx.x & 31;
    const int q = blockIdx.x * 8 + warp;
    __shared__ float sd[8][T_SEL];
    __shared__ int   si[8][T_SEL];
    if (q >= N_PTS) return;

    const float4* fb = (const float4*)g_feat;
    float4 qv[4];
#pragma unroll
    for (int j = 0; j < 4; j++) qv[j] = fb[(size_t)q * 128 + l + 32 * j];
    float sqq = g_sq[q];

    for (int c = 0; c < T_SEL; c += 2) {
        int i0 = g_mrg_i[(size_t)q * T_SEL + c];
        int i1 = g_mrg_i[(size_t)q * T_SEL + c + 1];
        float a0 = 0.f, a1 = 0.f;
#pragma unroll
        for (int j = 0; j < 4; j++) {
            float4 v0 = fb[(size_t)i0 * 128 + l + 32 * j];
            float4 v1 = fb[(size_t)i1 * 128 + l + 32 * j];
            a0 = fmaf(qv[j].x, v0.x, a0); a0 = fmaf(qv[j].y, v0.y, a0);
            a0 = fmaf(qv[j].z, v0.z, a0); a0 = fmaf(qv[j].w, v0.w, a0);
            a1 = fmaf(qv[j].x, v1.x, a1); a1 = fmaf(qv[j].y, v1.y, a1);
            a1 = fmaf(qv[j].z, v1.z, a1); a1 = fmaf(qv[j].w, v1.w, a1);
        }
#pragma unroll
        for (int o = 16; o > 0; o >>= 1) {
            a0 += __shfl_xor_sync(0xFFFFFFFF, a0, o);
            a1 += __shfl_xor_sync(0xFFFFFFFF, a1, o);
        }
        if (l == 0) {
            sd[warp][c]     = sqq + g_sq[i0] - 2.f * a0;
            si[warp][c]     = i0;
            sd[warp][c + 1] = sqq + g_sq[i1] - 2.f * a1;
            si[warp][c + 1] = i1;
        }
    }
    __syncwarp();

    if (l == 0) {
        float kd[KNN]; int ki[KNN];
#pragma unroll
        for (int t = 0; t < KNN; t++) { kd[t] = INFINITY; ki[t] = 0; }
        float kmax = INFINITY; int kpos = 0;
#pragma unroll
        for (int c = 0; c < T_SEL; c++) {
            float dd = sd[warp][c];
            if (dd < kmax) {
                kd[kpos] = dd; ki[kpos] = si[warp][c];
                kmax = kd[0]; kpos = 0;
#pragma unroll
                for (int t = 1; t < KNN; t++)
                    if (kd[t] > kmax) { kmax = kd[t]; kpos = t; }
            }
        }
        int cnt[NCLS];
#pragma unroll
        for (int c = 0; c < NCLS; c++) cnt[c] = 0;
#pragma unroll
        for (int t = 0; t < KNN; t++) cnt[g_label[ki[t]]]++;
        float s = 0.f;
#pragma unroll
        for (int c = 0; c < NCLS; c++) {
            if (cnt[c] > 0) {
                float p = (float)cnt[c] * (1.f / 9.f);
                s -= p * logf(p + 1e-6f);
            }
        }
        out[q] = s * (1.f / logf(19.f));
    }
}

// ---------------- launch ----------------------------------------------------
extern "C" void kernel_launch(void* const* d_in, const int* in_sizes, int n_in,
                              void* d_out, int out_size) {
    const float* feats = (const float*)d_in[0];
    const float* outs  = (const float*)d_in[1];
    float* out = (float*)d_out;

    cudaFuncSetAttribute(phase1_kernel,
                         cudaFuncAttributeMaxDynamicSharedMemorySize, DYNSMEM);
    cudaFuncSetAttribute(merge_kernel,
                         cudaFuncAttributeMaxDynamicSharedMemorySize, MERGE_SMEM);

    cudaMemsetAsync(out, 0, (size_t)out_size * sizeof(float), 0);
    prep_kernel<<<(N_PAD + 255) / 256, 256>>>(feats, outs);
    {
        dim3 g(N_PAD / 32, C_DIM / 32), b(32, 32);
        split_kernel<<<g, b>>>(feats);
    }
    pad_kernel<<<1, 128>>>();                      // op #4 -> phase1 is op #5
    phase1_kernel<<<NBLK, NTH, DYNSMEM>>>();       // ncu target
    merge_kernel<<<NBLK, 512, MERGE_SMEM>>>();
    refine_kernel<<<(N_PTS + 7) / 8, 256>>>(out);
}